// round 10
// baseline (speedup 1.0000x reference)
#include <cuda_runtime.h>
#include <cstdint>

// DenseDilatedKnnGraph: B=8, C=32, N=4096, K=9, DILATION=2
// x: (B, C, N, 1) float32  ->  out: (2, B, N, 9) float32-encoded indices
// Arithmetic FROZEN to the R8/R9-passing kernels (bit-identical distances,
// identical stable (dist, idx) ordering). R10: 4-way candidate split for
// occupancy; per-group register top-17 + stable 4-way merge.

#define BN   8
#define CC   32
#define NN   4096
#define KOUT 9
#define K17  17      // only ranks 0..16 are ever emitted (even positions)
#define QT   64      // queries per CTA
#define CT   64      // candidates per staged tile
#define STRIDE 36    // floats per candidate row (32 + 4 pad); rows 16B-aligned
#define GRP  4       // candidate groups per CTA
#define GCAND 1024   // candidates per group (NN / GRP)

typedef unsigned long long u64;

__device__ __forceinline__ u64 fma2(u64 a, u64 b, u64 c) {
    u64 d;
    asm("fma.rn.f32x2 %0, %1, %2, %3;" : "=l"(d) : "l"(a), "l"(b), "l"(c));
    return d;
}
__device__ __forceinline__ u64 pack2(float lo, float hi) {
    u64 r;
    asm("mov.b64 %0, {%1, %2};" : "=l"(r) : "f"(lo), "f"(hi));
    return r;
}
__device__ __forceinline__ void unpack2(u64 v, float& lo, float& hi) {
    asm("mov.b64 {%0, %1}, %2;" : "=f"(lo), "=f"(hi) : "l"(v));
}

__global__ __launch_bounds__(256, 3)
void knn_dilated_kernel(const float* __restrict__ x, float* __restrict__ out) {
    // 4 candidate tiles; reused as merge scratch after the main loop.
    __shared__ __align__(16) float pool[GRP * CT * STRIDE];  // 36864 B
    __shared__ float ssq[GRP * CT];                          // 1 KB

    const int tid = threadIdx.x;
    const int g   = tid >> 6;          // candidate group 0..3 (2 warps each)
    const int t   = tid & 63;          // query lane within CTA
    const int b   = blockIdx.y;
    const int qbase = blockIdx.x * QT;
    const int n   = qbase + t;
    const float* __restrict__ xb = x + (size_t)b * CC * NN;

    // ---- query point; sqn via the SAME serial fmaf chain as R8/R9 ----
    float sqn = 0.f;
    u64 qp[CC / 2];
#pragma unroll
    for (int i = 0; i < CC / 2; ++i) {
        float q0 = xb[(2 * i)     * NN + n];
        float q1 = xb[(2 * i + 1) * NN + n];
        sqn = fmaf(q0, q0, sqn);
        sqn = fmaf(q1, q1, sqn);
        qp[i] = pack2(q0, q1);
    }

    float topd[K17];
    int   topi[K17];
#pragma unroll
    for (int j = 0; j < K17; ++j) { topd[j] = INFINITY; topi[j] = 0; }

    float* mytile = pool + g * (CT * STRIDE);
    const int cand0 = g * GCAND;

    for (int tl = 0; tl < GCAND / CT; ++tl) {
        const int cbase = cand0 + tl * CT;
        __syncthreads();
        {   // stage tile (candidate-major) + norms (same fmaf chain as before)
            float s = 0.f;
#pragma unroll
            for (int c = 0; c < CC; ++c) {
                float v = xb[c * NN + cbase + t];
                mytile[t * STRIDE + c] = v;
                s = fmaf(v, v, s);
            }
            ssq[g * CT + t] = s;
        }
        __syncthreads();

#pragma unroll 2
        for (int tt = 0; tt < CT; ++tt) {
            const ulonglong2* cp = (const ulonglong2*)(mytile + tt * STRIDE);
            u64 acc0 = 0ull, acc1 = 0ull;   // lanes (a0,a1) and (a2,a3)
#pragma unroll
            for (int j = 0; j < 8; ++j) {
                ulonglong2 v = cp[j];        // LDS.128 broadcast (uniform tt)
                acc0 = fma2(qp[2 * j],     v.x, acc0);
                acc1 = fma2(qp[2 * j + 1], v.y, acc1);
            }
            float a0, a1, a2, a3;
            unpack2(acc0, a0, a1);
            unpack2(acc1, a2, a3);
            float dot  = (a0 + a1) + (a2 + a3);          // same reduce order
            float dist = __fadd_rn(__fsub_rn(sqn, __fmul_rn(2.0f, dot)),
                                   ssq[g * CT + tt]);

            if (dist < topd[K17 - 1]) {
                // Parallel sorted insert (latency-free), stable strict '<'.
                const int ci = cbase + tt;
                bool pb_hi = true;
#pragma unroll
                for (int j = K17 - 1; j > 0; --j) {
                    const bool pb_lo = dist < topd[j - 1];
                    topd[j] = fmaxf(topd[j - 1], fminf(topd[j], dist));
                    topi[j] = pb_lo ? topi[j - 1] : (pb_hi ? ci : topi[j]);
                    pb_hi = pb_lo;
                }
                topi[0] = pb_hi ? ci : topi[0];
                topd[0] = fminf(topd[0], dist);
            }
        }
    }

    // ---- merge the four per-group sorted lists (stable, SMEM) ----
    __syncthreads();                        // main-loop tile reads done
    float* sdist = pool;                    // GRP*QT*17 floats = 17408 B
    int*   sidx  = (int*)pool + GRP * QT * K17;
    {
        const int base = (g * QT + t) * K17;
#pragma unroll
        for (int j = 0; j < K17; ++j) {
            sdist[base + j] = topd[j];
            sidx[base + j]  = topi[j];
        }
    }
    __syncthreads();

    if (tid < QT) {
        const float* d0 = sdist + (0 * QT + t) * K17;
        const float* d1 = sdist + (1 * QT + t) * K17;
        const float* d2 = sdist + (2 * QT + t) * K17;
        const float* d3 = sdist + (3 * QT + t) * K17;
        const int*   x0 = sidx  + (0 * QT + t) * K17;
        const int*   x1 = sidx  + (1 * QT + t) * K17;
        const int*   x2 = sidx  + (2 * QT + t) * K17;
        const int*   x3 = sidx  + (3 * QT + t) * K17;
        const size_t base0 = ((size_t)b * NN + n) * KOUT;

        int i0 = 0, i1 = 0, i2 = 0, i3 = 0;
#pragma unroll
        for (int r = 0; r < K17; ++r) {
            const float a0 = d0[i0], a1 = d1[i1], a2 = d2[i2], a3 = d3[i3];
            // strict '<' everywhere: lower group (lower indices) wins ties,
            // reproducing single-pass stable order exactly.
            const bool t01 = a1 < a0;
            const bool t23 = a3 < a2;
            const float d01 = t01 ? a1 : a0;
            const float d23 = t23 ? a3 : a2;
            const bool th = d23 < d01;
            int idx;
            if (th) { if (t23) idx = x3[i3++]; else idx = x2[i2++]; }
            else    { if (t01) idx = x1[i1++]; else idx = x0[i0++]; }
            if ((r & 1) == 0) out[base0 + (r >> 1)] = (float)idx;
        }
    }

    // ---- center half: out[1,b,qbase..qbase+63,k] = n, spread over CTA ----
    {
        const size_t base1 = (size_t)BN * NN * KOUT
                           + ((size_t)b * NN + qbase) * KOUT;
        for (int k2 = tid; k2 < QT * KOUT; k2 += 256)
            out[base1 + k2] = (float)(qbase + k2 / KOUT);
    }
}

extern "C" void kernel_launch(void* const* d_in, const int* in_sizes, int n_in,
                              void* d_out, int out_size) {
    const float* x = (const float*)d_in[0];
    float* out = (float*)d_out;
    knn_dilated_kernel<<<dim3(NN / QT, BN), dim3(256)>>>(x, out);
}

// round 13
// speedup vs baseline: 1.2044x; 1.2044x over previous
#include <cuda_runtime.h>
#include <cstdint>

// DenseDilatedKnnGraph: B=8, C=32, N=4096, K=9, DILATION=2
// x: (B, C, N, 1) float32  ->  out: (2, B, N, 9) float32-encoded indices
// Arithmetic FROZEN to R8/R9 (bit-identical distances + stable ordering).
// R11 = R9 structure (2-way candidate split) + buffered insert: lanes append
// passing candidates to a tiny SMEM buffer; the 17-deep insert network runs
// only on warp-wide flushes. Provably bit-identical output to R9.

#define BN   8
#define CC   32
#define NN   4096
#define KOUT 9
#define K17  17      // only ranks 0..16 are ever emitted (even positions)
#define QT   128     // queries per CTA
#define CT   128     // candidates per staged tile
#define STRIDE 36    // floats per candidate row (32 + 4 pad); rows 16B-aligned
#define HALF 2048    // candidates per group
#define CAP  5       // per-thread append buffer slots (SMEM budget bound)

typedef unsigned long long u64;

__device__ __forceinline__ u64 fma2(u64 a, u64 b, u64 c) {
    u64 d;
    asm("fma.rn.f32x2 %0, %1, %2, %3;" : "=l"(d) : "l"(a), "l"(b), "l"(c));
    return d;
}
__device__ __forceinline__ u64 pack2(float lo, float hi) {
    u64 r;
    asm("mov.b64 %0, {%1, %2};" : "=l"(r) : "f"(lo), "f"(hi));
    return r;
}
__device__ __forceinline__ void unpack2(u64 v, float& lo, float& hi) {
    asm("mov.b64 {%0, %1}, %2;" : "=f"(lo), "=f"(hi) : "l"(v));
}

__global__ __launch_bounds__(256, 3)
void knn_dilated_kernel(const float* __restrict__ x, float* __restrict__ out) {
    __shared__ __align__(16) float pool[2 * CT * STRIDE];   // 36864 B
    __shared__ float ssq[2 * CT];                           //  1024 B
    __shared__ u64  sbuf[256 * CAP];                        // 10240 B

    const int tid = threadIdx.x;
    const int g   = tid >> 7;          // candidate-half group 0/1
    const int t   = tid & 127;         // query lane within CTA
    const int b   = blockIdx.y;
    const int n   = blockIdx.x * QT + t;
    const float* __restrict__ xb = x + (size_t)b * CC * NN;

    // ---- query point; sqn via the SAME serial fmaf chain as R8/R9 ----
    float sqn = 0.f;
    u64 qp[CC / 2];
#pragma unroll
    for (int i = 0; i < CC / 2; ++i) {
        float q0 = xb[(2 * i)     * NN + n];
        float q1 = xb[(2 * i + 1) * NN + n];
        sqn = fmaf(q0, q0, sqn);
        sqn = fmaf(q1, q1, sqn);
        qp[i] = pack2(q0, q1);
    }

    float topd[K17];
    int   topi[K17];
#pragma unroll
    for (int j = 0; j < K17; ++j) { topd[j] = INFINITY; topi[j] = 0; }

    float* mytile = pool + g * (CT * STRIDE);
    u64*   mybuf  = sbuf + tid * CAP;
    int    nb     = 0;
    const int cand0 = g * HALF;

    for (int tl = 0; tl < HALF / CT; ++tl) {
        const int cbase = cand0 + tl * CT;
        __syncthreads();
        {   // stage candidate tile (candidate-major) + norms (frozen chain)
            float s = 0.f;
#pragma unroll
            for (int c = 0; c < CC; ++c) {
                float v = xb[c * NN + cbase + t];
                mytile[t * STRIDE + c] = v;
                s = fmaf(v, v, s);
            }
            ssq[g * CT + t] = s;
        }
        __syncthreads();

#pragma unroll 2
        for (int tt = 0; tt < CT; ++tt) {
            const ulonglong2* cp = (const ulonglong2*)(mytile + tt * STRIDE);
            u64 acc0 = 0ull, acc1 = 0ull;   // lanes (a0,a1) and (a2,a3)
#pragma unroll
            for (int j = 0; j < 8; ++j) {
                ulonglong2 v = cp[j];        // LDS.128 broadcast (uniform tt)
                acc0 = fma2(qp[2 * j],     v.x, acc0);
                acc1 = fma2(qp[2 * j + 1], v.y, acc1);
            }
            float a0, a1, a2, a3;
            unpack2(acc0, a0, a1);
            unpack2(acc1, a2, a3);
            float dot  = (a0 + a1) + (a2 + a3);          // same reduce order
            float dist = __fadd_rn(__fsub_rn(sqn, __fmul_rn(2.0f, dot)),
                                   ssq[g * CT + tt]);

            // append (cheap) instead of running the network per candidate;
            // stale threshold is a superset filter -> no accepted cand lost
            if (dist < topd[K17 - 1]) {
                mybuf[nb++] = ((u64)__float_as_uint(dist) << 32)
                            | (u64)(unsigned)(cbase + tt);
            }
            if (__any_sync(0xffffffffu, nb == CAP)) {
                // warp-wide flush: replay buffered candidates IN ORDER through
                // the unchanged R9 guard + network => bit-identical evolution
#pragma unroll
                for (int e = 0; e < CAP; ++e) {
                    float cd = INFINITY;
                    int   ci = 0;
                    if (e < nb) {
                        u64 pk = mybuf[e];
                        cd = __uint_as_float((unsigned)(pk >> 32));
                        ci = (int)(unsigned)pk;
                    }
                    if (cd < topd[K17 - 1]) {
                        bool pb_hi = true;
#pragma unroll
                        for (int j = K17 - 1; j > 0; --j) {
                            const bool pb_lo = cd < topd[j - 1];
                            topd[j] = fmaxf(topd[j - 1], fminf(topd[j], cd));
                            topi[j] = pb_lo ? topi[j - 1] : (pb_hi ? ci : topi[j]);
                            pb_hi = pb_lo;
                        }
                        topi[0] = pb_hi ? ci : topi[0];
                        topd[0] = fminf(topd[0], cd);
                    }
                }
                nb = 0;
            }
        }
    }

    // ---- final flush of remaining buffered candidates ----
#pragma unroll
    for (int e = 0; e < CAP; ++e) {
        float cd = INFINITY;
        int   ci = 0;
        if (e < nb) {
            u64 pk = mybuf[e];
            cd = __uint_as_float((unsigned)(pk >> 32));
            ci = (int)(unsigned)pk;
        }
        if (cd < topd[K17 - 1]) {
            bool pb_hi = true;
#pragma unroll
            for (int j = K17 - 1; j > 0; --j) {
                const bool pb_lo = cd < topd[j - 1];
                topd[j] = fmaxf(topd[j - 1], fminf(topd[j], cd));
                topi[j] = pb_lo ? topi[j - 1] : (pb_hi ? ci : topi[j]);
                pb_hi = pb_lo;
            }
            topi[0] = pb_hi ? ci : topi[0];
            topd[0] = fminf(topd[0], cd);
        }
    }

    // ---- merge the two per-group sorted lists (stable, SMEM) ----
    __syncthreads();                       // main-loop tile reads done
    float* sdist = pool;                   // 2*128*17 floats = 17408 B
    int*   sidx  = (int*)pool + 2 * 128 * K17;
    {
        const int base = (g * 128 + t) * K17;
#pragma unroll
        for (int j = 0; j < K17; ++j) {
            sdist[base + j] = topd[j];
            sidx[base + j]  = topi[j];
        }
    }
    __syncthreads();

    if (tid < 128) {
        const float* d0 = sdist + t * K17;
        const float* d1 = sdist + (128 + t) * K17;
        const int*   x0 = sidx  + t * K17;
        const int*   x1 = sidx  + (128 + t) * K17;
        const size_t base0 = ((size_t)b * NN + n) * KOUT;
        const size_t base1 = (size_t)BN * NN * KOUT + base0;

        int i = 0, j = 0;
#pragma unroll
        for (int r = 0; r < K17; ++r) {
            const float a = d0[i], bb = d1[j];
            // group 0 (lower indices) wins exact-distance ties == stable order
            const bool take0 = !(bb < a);
            const int idx = take0 ? x0[i] : x1[j];
            if ((r & 1) == 0) out[base0 + (r >> 1)] = (float)idx;
            i += take0 ? 1 : 0;
            j += take0 ? 0 : 1;
        }
        const float nf = (float)n;
#pragma unroll
        for (int k = 0; k < KOUT; ++k) out[base1 + k] = nf;
    }
}

extern "C" void kernel_launch(void* const* d_in, const int* in_sizes, int n_in,
                              void* d_out, int out_size) {
    const float* x = (const float*)d_in[0];
    float* out = (float*)d_out;
    knn_dilated_kernel<<<dim3(NN / QT, BN), dim3(256)>>>(x, out);
}

// round 14
// speedup vs baseline: 1.2382x; 1.0281x over previous
#include <cuda_runtime.h>
#include <cstdint>

// DenseDilatedKnnGraph: B=8, C=32, N=4096, K=9, DILATION=2
// x: (B, C, N, 1) float32  ->  out: (2, B, N, 9) float32-encoded indices
// Arithmetic FROZEN to R8/R9/R13 (bit-identical distances + stable ordering).
// R14: two-pass. Pass 1: 4-way candidate split ACROSS CTAs (grid 1024) for
// occupancy; per-(query,range) sorted top-17 via buffered insert -> scratch.
// Pass 2: stable 4-way merge by order-preserving u64 key (== R10 semantics).

#define BN   8
#define CC   32
#define NN   4096
#define KOUT 9
#define K17  17      // only ranks 0..16 are ever emitted (even positions)
#define QT   128     // queries per CTA (pass 1)
#define CT   128     // candidates per staged tile
#define STRIDE 36    // floats per candidate row (32 + 4 pad); rows 16B-aligned
#define NSPLIT 4
#define GCAND (NN / NSPLIT)   // 1024 candidates per CTA range
#define CAP  5       // per-thread append buffer slots

typedef unsigned long long u64;

__device__ u64 g_scratch[(size_t)BN * NN * NSPLIT * K17];   // 17.8 MB

__device__ __forceinline__ u64 fma2(u64 a, u64 b, u64 c) {
    u64 d;
    asm("fma.rn.f32x2 %0, %1, %2, %3;" : "=l"(d) : "l"(a), "l"(b), "l"(c));
    return d;
}
__device__ __forceinline__ u64 pack2(float lo, float hi) {
    u64 r;
    asm("mov.b64 %0, {%1, %2};" : "=l"(r) : "f"(lo), "f"(hi));
    return r;
}
__device__ __forceinline__ void unpack2(u64 v, float& lo, float& hi) {
    asm("mov.b64 {%0, %1}, %2;" : "=f"(lo), "=f"(hi) : "l"(v));
}
// order-preserving float -> uint (handles negatives; monotone)
__device__ __forceinline__ unsigned ford(float f) {
    unsigned u = __float_as_uint(f);
    return u ^ ((u >> 31) ? 0xFFFFFFFFu : 0x80000000u);
}

// ---------------- pass 1: per-range top-17 ----------------
__global__ __launch_bounds__(QT, 6)
void knn_pass1(const float* __restrict__ x) {
    __shared__ __align__(16) float stile[CT * STRIDE];      // 18432 B
    __shared__ float ssq[CT];                               //   512 B
    __shared__ u64  sbuf[QT * CAP];                         //  5120 B

    const int t = threadIdx.x;
    const int b = blockIdx.y;
    const int s = blockIdx.z;
    const int n = blockIdx.x * QT + t;
    const float* __restrict__ xb = x + (size_t)b * CC * NN;

    // query point; sqn via the SAME serial fmaf chain (frozen)
    float sqn = 0.f;
    u64 qp[CC / 2];
#pragma unroll
    for (int i = 0; i < CC / 2; ++i) {
        float q0 = xb[(2 * i)     * NN + n];
        float q1 = xb[(2 * i + 1) * NN + n];
        sqn = fmaf(q0, q0, sqn);
        sqn = fmaf(q1, q1, sqn);
        qp[i] = pack2(q0, q1);
    }

    float topd[K17];
    int   topi[K17];
#pragma unroll
    for (int j = 0; j < K17; ++j) { topd[j] = INFINITY; topi[j] = 0; }

    u64* mybuf = sbuf + t * CAP;
    int  nb = 0;
    const int cand0 = s * GCAND;

    for (int tl = 0; tl < GCAND / CT; ++tl) {
        const int cbase = cand0 + tl * CT;
        __syncthreads();
        {   // stage tile (candidate-major) + norms (frozen chain)
            float sum = 0.f;
#pragma unroll
            for (int c = 0; c < CC; ++c) {
                float v = xb[c * NN + cbase + t];
                stile[t * STRIDE + c] = v;
                sum = fmaf(v, v, sum);
            }
            ssq[t] = sum;
        }
        __syncthreads();

#pragma unroll 2
        for (int tt = 0; tt < CT; ++tt) {
            const ulonglong2* cp = (const ulonglong2*)(stile + tt * STRIDE);
            u64 acc0 = 0ull, acc1 = 0ull;
#pragma unroll
            for (int j = 0; j < 8; ++j) {
                ulonglong2 v = cp[j];        // LDS.128 broadcast (uniform tt)
                acc0 = fma2(qp[2 * j],     v.x, acc0);
                acc1 = fma2(qp[2 * j + 1], v.y, acc1);
            }
            float a0, a1, a2, a3;
            unpack2(acc0, a0, a1);
            unpack2(acc1, a2, a3);
            float dot  = (a0 + a1) + (a2 + a3);          // same reduce order
            float dist = __fadd_rn(__fsub_rn(sqn, __fmul_rn(2.0f, dot)),
                                   ssq[tt]);

            if (dist < topd[K17 - 1]) {   // stale-threshold superset filter
                mybuf[nb++] = ((u64)__float_as_uint(dist) << 32)
                            | (u64)(unsigned)(cbase + tt);
            }
            if (__any_sync(0xffffffffu, nb == CAP)) {
                // warp-wide flush: replay in order through the frozen network
#pragma unroll
                for (int e = 0; e < CAP; ++e) {
                    float cd = INFINITY;
                    int   ci = 0;
                    if (e < nb) {
                        u64 pk = mybuf[e];
                        cd = __uint_as_float((unsigned)(pk >> 32));
                        ci = (int)(unsigned)pk;
                    }
                    if (cd < topd[K17 - 1]) {
                        bool pb_hi = true;
#pragma unroll
                        for (int j = K17 - 1; j > 0; --j) {
                            const bool pb_lo = cd < topd[j - 1];
                            topd[j] = fmaxf(topd[j - 1], fminf(topd[j], cd));
                            topi[j] = pb_lo ? topi[j - 1] : (pb_hi ? ci : topi[j]);
                            pb_hi = pb_lo;
                        }
                        topi[0] = pb_hi ? ci : topi[0];
                        topd[0] = fminf(topd[0], cd);
                    }
                }
                nb = 0;
            }
        }
    }

    // final flush
#pragma unroll
    for (int e = 0; e < CAP; ++e) {
        float cd = INFINITY;
        int   ci = 0;
        if (e < nb) {
            u64 pk = mybuf[e];
            cd = __uint_as_float((unsigned)(pk >> 32));
            ci = (int)(unsigned)pk;
        }
        if (cd < topd[K17 - 1]) {
            bool pb_hi = true;
#pragma unroll
            for (int j = K17 - 1; j > 0; --j) {
                const bool pb_lo = cd < topd[j - 1];
                topd[j] = fmaxf(topd[j - 1], fminf(topd[j], cd));
                topi[j] = pb_lo ? topi[j - 1] : (pb_hi ? ci : topi[j]);
                pb_hi = pb_lo;
            }
            topi[0] = pb_hi ? ci : topi[0];
            topd[0] = fminf(topd[0], cd);
        }
    }

    // write sorted list with order-preserving key (dist asc, idx tiebreak)
    u64* dst = g_scratch + (((size_t)b * NN + n) * NSPLIT + s) * K17;
#pragma unroll
    for (int j = 0; j < K17; ++j)
        dst[j] = ((u64)ford(topd[j]) << 32) | (u64)(unsigned)topi[j];
}

// ---------------- pass 2: stable 4-way merge + emit ----------------
__global__ __launch_bounds__(256)
void knn_pass2(float* __restrict__ out) {
    const int qq = blockIdx.x * 256 + threadIdx.x;   // 0 .. B*N-1
    const int n  = qq & (NN - 1);
    const u64* l0 = g_scratch + ((size_t)qq * NSPLIT + 0) * K17;
    const u64* l1 = g_scratch + ((size_t)qq * NSPLIT + 1) * K17;
    const u64* l2 = g_scratch + ((size_t)qq * NSPLIT + 2) * K17;
    const u64* l3 = g_scratch + ((size_t)qq * NSPLIT + 3) * K17;

    int i0 = 0, i1 = 0, i2 = 0, i3 = 0;
    u64 h0 = l0[0], h1 = l1[0], h2 = l2[0], h3 = l3[0];
    const u64 SENT = ~0ull;

    const size_t base0 = (size_t)qq * KOUT;
    const size_t base1 = (size_t)BN * NN * KOUT + base0;

#pragma unroll
    for (int r = 0; r < K17; ++r) {
        // min over 4 heads; u64 key order == (dist asc, idx asc) == stable
        const u64 m01 = (h1 < h0) ? h1 : h0;
        const u64 m23 = (h3 < h2) ? h3 : h2;
        const u64 m   = (m23 < m01) ? m23 : m01;
        if ((r & 1) == 0) out[base0 + (r >> 1)] = (float)(unsigned)m;
        if (m == h0)      { ++i0; h0 = (i0 < K17) ? l0[i0] : SENT; }
        else if (m == h1) { ++i1; h1 = (i1 < K17) ? l1[i1] : SENT; }
        else if (m == h2) { ++i2; h2 = (i2 < K17) ? l2[i2] : SENT; }
        else              { ++i3; h3 = (i3 < K17) ? l3[i3] : SENT; }
    }
    const float nf = (float)n;
#pragma unroll
    for (int k = 0; k < KOUT; ++k) out[base1 + k] = nf;
}

extern "C" void kernel_launch(void* const* d_in, const int* in_sizes, int n_in,
                              void* d_out, int out_size) {
    const float* x = (const float*)d_in[0];
    float* out = (float*)d_out;
    knn_pass1<<<dim3(NN / QT, BN, NSPLIT), dim3(QT)>>>(x);
    knn_pass2<<<dim3(BN * NN / 256), dim3(256)>>>(out);
}

// round 16
// speedup vs baseline: 1.9067x; 1.5399x over previous
#include <cuda_runtime.h>
#include <cstdint>

// DenseDilatedKnnGraph: B=8, C=32, N=4096, K=9, DILATION=2
// x: (B, C, N, 1) float32  ->  out: (2, B, N, 9) float32-encoded indices
// Arithmetic FROZEN to R8..R14 (bit-identical distances + stable ordering).
// R15: 4-candidate-blocked inner loop. 8 independent FMA chains, one
// fmin-tree guard + one ballot per 4 candidates (amortizes the serial
// epilogue/vote latency that capped issue at ~40%). Buffered-insert replay
// (exact guard, in-order) is unchanged => output bit-identical to R13/R14.

#define BN   8
#define CC   32
#define NN   4096
#define KOUT 9
#define K17  17      // only ranks 0..16 are ever emitted (even positions)
#define QT   128     // queries per CTA (pass 1)
#define CT   128     // candidates per staged tile
#define STRIDE 36    // floats per candidate row (32 + 4 pad); rows 16B-aligned
#define NSPLIT 4
#define GCAND (NN / NSPLIT)   // 1024 candidates per CTA range
#define CAP  8       // per-thread append buffer slots

typedef unsigned long long u64;

__device__ u64 g_scratch[(size_t)BN * NN * NSPLIT * K17];   // 17.8 MB

__device__ __forceinline__ u64 fma2(u64 a, u64 b, u64 c) {
    u64 d;
    asm("fma.rn.f32x2 %0, %1, %2, %3;" : "=l"(d) : "l"(a), "l"(b), "l"(c));
    return d;
}
__device__ __forceinline__ u64 pack2(float lo, float hi) {
    u64 r;
    asm("mov.b64 %0, {%1, %2};" : "=l"(r) : "f"(lo), "f"(hi));
    return r;
}
__device__ __forceinline__ void unpack2(u64 v, float& lo, float& hi) {
    asm("mov.b64 {%0, %1}, %2;" : "=f"(lo), "=f"(hi) : "l"(v));
}
// order-preserving float -> uint (monotone, handles sign)
__device__ __forceinline__ unsigned ford(float f) {
    unsigned u = __float_as_uint(f);
    return u ^ ((u >> 31) ? 0xFFFFFFFFu : 0x80000000u);
}

// exact sequential insert (frozen R9 network) — used only in flush replay
__device__ __forceinline__ void insert17(float cd, int ci,
                                         float* topd, int* topi) {
    if (cd < topd[K17 - 1]) {
        bool pb_hi = true;
#pragma unroll
        for (int j = K17 - 1; j > 0; --j) {
            const bool pb_lo = cd < topd[j - 1];
            topd[j] = fmaxf(topd[j - 1], fminf(topd[j], cd));
            topi[j] = pb_lo ? topi[j - 1] : (pb_hi ? ci : topi[j]);
            pb_hi = pb_lo;
        }
        topi[0] = pb_hi ? ci : topi[0];
        topd[0] = fminf(topd[0], cd);
    }
}

// ---------------- pass 1: per-range top-17 ----------------
__global__ __launch_bounds__(QT, 4)
void knn_pass1(const float* __restrict__ x) {
    __shared__ __align__(16) float stile[CT * STRIDE];      // 18432 B
    __shared__ float ssq[CT];                               //   512 B
    __shared__ u64  sbuf[QT * CAP];                         //  8192 B

    const int t = threadIdx.x;
    const int b = blockIdx.y;
    const int s = blockIdx.z;
    const int n = blockIdx.x * QT + t;
    const float* __restrict__ xb = x + (size_t)b * CC * NN;

    // query point; sqn via the SAME serial fmaf chain (frozen)
    float sqn = 0.f;
    u64 qp[CC / 2];
#pragma unroll
    for (int i = 0; i < CC / 2; ++i) {
        float q0 = xb[(2 * i)     * NN + n];
        float q1 = xb[(2 * i + 1) * NN + n];
        sqn = fmaf(q0, q0, sqn);
        sqn = fmaf(q1, q1, sqn);
        qp[i] = pack2(q0, q1);
    }

    float topd[K17];
    int   topi[K17];
#pragma unroll
    for (int j = 0; j < K17; ++j) { topd[j] = INFINITY; topi[j] = 0; }

    u64* mybuf = sbuf + t * CAP;
    int  nb = 0;
    const int cand0 = s * GCAND;

    for (int tl = 0; tl < GCAND / CT; ++tl) {
        const int cbase = cand0 + tl * CT;
        __syncthreads();
        {   // stage tile (candidate-major) + norms (frozen chain)
            float sum = 0.f;
#pragma unroll
            for (int c = 0; c < CC; ++c) {
                float v = xb[c * NN + cbase + t];
                stile[t * STRIDE + c] = v;
                sum = fmaf(v, v, sum);
            }
            ssq[t] = sum;
        }
        __syncthreads();

        for (int t4 = 0; t4 < CT; t4 += 4) {
            const ulonglong2* cp0 = (const ulonglong2*)(stile + (t4 + 0) * STRIDE);
            const ulonglong2* cp1 = (const ulonglong2*)(stile + (t4 + 1) * STRIDE);
            const ulonglong2* cp2 = (const ulonglong2*)(stile + (t4 + 2) * STRIDE);
            const ulonglong2* cp3 = (const ulonglong2*)(stile + (t4 + 3) * STRIDE);
            // 8 independent accumulator chains (2 per candidate, frozen split)
            u64 A0 = 0, B0 = 0, A1 = 0, B1 = 0, A2 = 0, B2 = 0, A3 = 0, B3 = 0;
#pragma unroll
            for (int j = 0; j < 8; ++j) {
                ulonglong2 v0 = cp0[j];
                ulonglong2 v1 = cp1[j];
                ulonglong2 v2 = cp2[j];
                ulonglong2 v3 = cp3[j];
                A0 = fma2(qp[2 * j],     v0.x, A0);
                B0 = fma2(qp[2 * j + 1], v0.y, B0);
                A1 = fma2(qp[2 * j],     v1.x, A1);
                B1 = fma2(qp[2 * j + 1], v1.y, B1);
                A2 = fma2(qp[2 * j],     v2.x, A2);
                B2 = fma2(qp[2 * j + 1], v2.y, B2);
                A3 = fma2(qp[2 * j],     v3.x, A3);
                B3 = fma2(qp[2 * j + 1], v3.y, B3);
            }
            float d[4];
            {
                float a0, a1, a2, a3;
                unpack2(A0, a0, a1); unpack2(B0, a2, a3);
                float dot = (a0 + a1) + (a2 + a3);      // frozen reduce order
                d[0] = __fadd_rn(__fsub_rn(sqn, __fmul_rn(2.0f, dot)), ssq[t4 + 0]);
                unpack2(A1, a0, a1); unpack2(B1, a2, a3);
                dot = (a0 + a1) + (a2 + a3);
                d[1] = __fadd_rn(__fsub_rn(sqn, __fmul_rn(2.0f, dot)), ssq[t4 + 1]);
                unpack2(A2, a0, a1); unpack2(B2, a2, a3);
                dot = (a0 + a1) + (a2 + a3);
                d[2] = __fadd_rn(__fsub_rn(sqn, __fmul_rn(2.0f, dot)), ssq[t4 + 2]);
                unpack2(A3, a0, a1); unpack2(B3, a2, a3);
                dot = (a0 + a1) + (a2 + a3);
                d[3] = __fadd_rn(__fsub_rn(sqn, __fmul_rn(2.0f, dot)), ssq[t4 + 3]);
            }

            // one guard for 4 candidates (stale threshold = superset filter;
            // exactness restored by the in-order flush replay below)
            const float thr  = topd[K17 - 1];
            const float dmin = fminf(fminf(d[0], d[1]), fminf(d[2], d[3]));
            if (dmin < thr) {
#pragma unroll
                for (int cc = 0; cc < 4; ++cc)
                    if (d[cc] < thr)
                        mybuf[nb++] = ((u64)__float_as_uint(d[cc]) << 32)
                                    | (u64)(unsigned)(cbase + t4 + cc);
            }
            // one vote per 4 candidates; nb can grow by <=4 between votes,
            // flush at nb>=CAP-3 guarantees nb<=CAP always
            if (__any_sync(0xffffffffu, nb >= CAP - 3)) {
#pragma unroll
                for (int e = 0; e < CAP; ++e) {
                    float cd = INFINITY;
                    int   ci = 0;
                    if (e < nb) {
                        u64 pk = mybuf[e];
                        cd = __uint_as_float((unsigned)(pk >> 32));
                        ci = (int)(unsigned)pk;
                    }
                    insert17(cd, ci, topd, topi);
                }
                nb = 0;
            }
        }
    }

    // final flush
#pragma unroll
    for (int e = 0; e < CAP; ++e) {
        float cd = INFINITY;
        int   ci = 0;
        if (e < nb) {
            u64 pk = mybuf[e];
            cd = __uint_as_float((unsigned)(pk >> 32));
            ci = (int)(unsigned)pk;
        }
        insert17(cd, ci, topd, topi);
    }

    // write sorted list with order-preserving key (dist asc, idx tiebreak)
    u64* dst = g_scratch + (((size_t)b * NN + n) * NSPLIT + s) * K17;
#pragma unroll
    for (int j = 0; j < K17; ++j)
        dst[j] = ((u64)ford(topd[j]) << 32) | (u64)(unsigned)topi[j];
}

// ---------------- pass 2: stable 4-way merge + emit ----------------
__global__ __launch_bounds__(256)
void knn_pass2(float* __restrict__ out) {
    const int qq = blockIdx.x * 256 + threadIdx.x;   // 0 .. B*N-1
    const int n  = qq & (NN - 1);
    const u64* l0 = g_scratch + ((size_t)qq * NSPLIT + 0) * K17;
    const u64* l1 = g_scratch + ((size_t)qq * NSPLIT + 1) * K17;
    const u64* l2 = g_scratch + ((size_t)qq * NSPLIT + 2) * K17;
    const u64* l3 = g_scratch + ((size_t)qq * NSPLIT + 3) * K17;

    int i0 = 0, i1 = 0, i2 = 0, i3 = 0;
    u64 h0 = l0[0], h1 = l1[0], h2 = l2[0], h3 = l3[0];
    const u64 SENT = ~0ull;

    const size_t base0 = (size_t)qq * KOUT;
    const size_t base1 = (size_t)BN * NN * KOUT + base0;

#pragma unroll
    for (int r = 0; r < K17; ++r) {
        // min over 4 heads; u64 key order == (dist asc, idx asc) == stable
        const u64 m01 = (h1 < h0) ? h1 : h0;
        const u64 m23 = (h3 < h2) ? h3 : h2;
        const u64 m   = (m23 < m01) ? m23 : m01;
        if ((r & 1) == 0) out[base0 + (r >> 1)] = (float)(unsigned)m;
        if (m == h0)      { ++i0; h0 = (i0 < K17) ? l0[i0] : SENT; }
        else if (m == h1) { ++i1; h1 = (i1 < K17) ? l1[i1] : SENT; }
        else if (m == h2) { ++i2; h2 = (i2 < K17) ? l2[i2] : SENT; }
        else              { ++i3; h3 = (i3 < K17) ? l3[i3] : SENT; }
    }
    const float nf = (float)n;
#pragma unroll
    for (int k = 0; k < KOUT; ++k) out[base1 + k] = nf;
}

extern "C" void kernel_launch(void* const* d_in, const int* in_sizes, int n_in,
                              void* d_out, int out_size) {
    const float* x = (const float*)d_in[0];
    float* out = (float*)d_out;
    knn_pass1<<<dim3(NN / QT, BN, NSPLIT), dim3(QT)>>>(x);
    knn_pass2<<<dim3(BN * NN / 256), dim3(256)>>>(out);
}